// round 3
// baseline (speedup 1.0000x reference)
#include <cuda_runtime.h>

// MaxPool3d k=2 s=2 fp32 [2,32,128,128,128] -> [2,32,64,64,64]
// Persistent single-wave grid-stride: 148 SMs x 8 CTAs x 256 thr, each thread
// loops over output quads (4 outputs along W per iteration, 8x float4 loads,
// 1x float4 store, streaming cache hints). No wave transitions; memory queues
// stay full for the whole kernel.

#define W_IN    128
#define HW_IN   (128 * 128)
#define DHW_IN  (128 * 128 * 128)
#define W_OUT   64
#define HW_OUT  (64 * 64)
#define DHW_OUT (64 * 64 * 64)

#define N_QUADS (64 * 64 * 64 * 64 / 4)   // 4,194,304 total float4 outputs

__global__ void __launch_bounds__(256) maxpool3d_k2s2_v3(
    const float* __restrict__ in, float* __restrict__ out)
{
    const int stride = gridDim.x * blockDim.x;

    for (int tid = blockIdx.x * blockDim.x + threadIdx.x; tid < N_QUADS; tid += stride) {
        // tid -> (bc, d, h, q), q in [0,16): outputs w = 4q..4q+3
        int q  = tid & 15;
        int t1 = tid >> 4;
        int h  = t1 & 63;
        int t2 = t1 >> 6;
        int d  = t2 & 63;
        int bc = t2 >> 6;            // 0..63

        const float4* base = reinterpret_cast<const float4*>(
            in + (size_t)bc * DHW_IN + (size_t)(2 * d) * HW_IN + (size_t)(2 * h) * W_IN)
            + 2 * q;

        float4 r0a = __ldcs(base);
        float4 r0b = __ldcs(base + 1);
        float4 r1a = __ldcs(base + (W_IN / 4));
        float4 r1b = __ldcs(base + (W_IN / 4) + 1);
        float4 r2a = __ldcs(base + (HW_IN / 4));
        float4 r2b = __ldcs(base + (HW_IN / 4) + 1);
        float4 r3a = __ldcs(base + (HW_IN / 4 + W_IN / 4));
        float4 r3b = __ldcs(base + (HW_IN / 4 + W_IN / 4) + 1);

        float4 res;
        res.x = fmaxf(fmaxf(fmaxf(r0a.x, r0a.y), fmaxf(r1a.x, r1a.y)),
                      fmaxf(fmaxf(r2a.x, r2a.y), fmaxf(r3a.x, r3a.y)));
        res.y = fmaxf(fmaxf(fmaxf(r0a.z, r0a.w), fmaxf(r1a.z, r1a.w)),
                      fmaxf(fmaxf(r2a.z, r2a.w), fmaxf(r3a.z, r3a.w)));
        res.z = fmaxf(fmaxf(fmaxf(r0b.x, r0b.y), fmaxf(r1b.x, r1b.y)),
                      fmaxf(fmaxf(r2b.x, r2b.y), fmaxf(r3b.x, r3b.y)));
        res.w = fmaxf(fmaxf(fmaxf(r0b.z, r0b.w), fmaxf(r1b.z, r1b.w)),
                      fmaxf(fmaxf(r2b.z, r2b.w), fmaxf(r3b.z, r3b.w)));

        float4* op = reinterpret_cast<float4*>(
            out + (size_t)bc * DHW_OUT + (size_t)d * HW_OUT + (size_t)h * W_OUT) + q;
        __stcs(op, res);
    }
}

extern "C" void kernel_launch(void* const* d_in, const int* in_sizes, int n_in,
                              void* d_out, int out_size)
{
    const float* in = (const float*)d_in[0];
    float* out = (float*)d_out;
    // Single wave: 152 SMs on GB300, 8 CTAs of 256 threads per SM fits (regs ~31).
    int blocks = 152 * 8;
    maxpool3d_k2s2_v3<<<blocks, 256>>>(in, out);
}

// round 4
// speedup vs baseline: 1.1133x; 1.1133x over previous
#include <cuda_runtime.h>

// MaxPool3d k=2 s=2 fp32 [2,32,128,128,128] -> [2,32,64,64,64]
// Multi-wave (best R2 shape): 4 outputs/thread along W, 8x float4 streaming
// loads, 1x float4 streaming store. Exact grid (no tail guard): 4,194,304
// quads / 512 threads = 8192 blocks.

#define W_IN    128
#define HW_IN   (128 * 128)
#define DHW_IN  (128 * 128 * 128)
#define W_OUT   64
#define HW_OUT  (64 * 64)
#define DHW_OUT (64 * 64 * 64)

__global__ void __launch_bounds__(512) maxpool3d_k2s2_v4(
    const float* __restrict__ in, float* __restrict__ out)
{
    int tid = blockIdx.x * blockDim.x + threadIdx.x;   // exact: no bounds check

    // tid -> (bc, d, h, q), q in [0,16): outputs w = 4q..4q+3
    int q  = tid & 15;
    int t1 = tid >> 4;
    int h  = t1 & 63;
    int t2 = t1 >> 6;
    int d  = t2 & 63;
    int bc = t2 >> 6;            // 0..63

    const float4* base = reinterpret_cast<const float4*>(
        in + (size_t)bc * DHW_IN + (size_t)(2 * d) * HW_IN + (size_t)(2 * h) * W_IN)
        + 2 * q;

    float4 r0a = __ldcs(base);
    float4 r0b = __ldcs(base + 1);
    float4 r1a = __ldcs(base + (W_IN / 4));
    float4 r1b = __ldcs(base + (W_IN / 4) + 1);
    float4 r2a = __ldcs(base + (HW_IN / 4));
    float4 r2b = __ldcs(base + (HW_IN / 4) + 1);
    float4 r3a = __ldcs(base + (HW_IN / 4 + W_IN / 4));
    float4 r3b = __ldcs(base + (HW_IN / 4 + W_IN / 4) + 1);

    float4 res;
    res.x = fmaxf(fmaxf(fmaxf(r0a.x, r0a.y), fmaxf(r1a.x, r1a.y)),
                  fmaxf(fmaxf(r2a.x, r2a.y), fmaxf(r3a.x, r3a.y)));
    res.y = fmaxf(fmaxf(fmaxf(r0a.z, r0a.w), fmaxf(r1a.z, r1a.w)),
                  fmaxf(fmaxf(r2a.z, r2a.w), fmaxf(r3a.z, r3a.w)));
    res.z = fmaxf(fmaxf(fmaxf(r0b.x, r0b.y), fmaxf(r1b.x, r1b.y)),
                  fmaxf(fmaxf(r2b.x, r2b.y), fmaxf(r3b.x, r3b.y)));
    res.w = fmaxf(fmaxf(fmaxf(r0b.z, r0b.w), fmaxf(r1b.z, r1b.w)),
                  fmaxf(fmaxf(r2b.z, r2b.w), fmaxf(r3b.z, r3b.w)));

    float4* op = reinterpret_cast<float4*>(
        out + (size_t)bc * DHW_OUT + (size_t)d * HW_OUT + (size_t)h * W_OUT) + q;
    __stcs(op, res);
}

extern "C" void kernel_launch(void* const* d_in, const int* in_sizes, int n_in,
                              void* d_out, int out_size)
{
    const float* in = (const float*)d_in[0];
    float* out = (float*)d_out;
    int n_quads = out_size / 4;              // 4,194,304 (divides 512 exactly)
    maxpool3d_k2s2_v4<<<n_quads / 512, 512>>>(in, out);
}